// round 5
// baseline (speedup 1.0000x reference)
#include <cuda_runtime.h>
#include <math.h>
#include <stdint.h>

#define D        2048
#define NEXP     64
#define TM       128                      // tokens per CTA (8 warps x 16 rows)
#define KC       32
#define NCHUNK   (D / KC)                 // 64
#define STAGES   6
#define NTOK     16384
#define TAU      0.25f

#define APITCH   36                       // floats per A row: ldmatrix rows land in distinct banks
#define A_BYTES  (TM * APITCH * 4)        // 18432
#define B_BYTES  (KC * NEXP * 4)          // 8192 (fragment-ordered)
#define STAGE_BYTES (A_BYTES + B_BYTES)   // 26624
#define SMEM_TOTAL  (STAGES * STAGE_BYTES) // 159744

__device__ float g_enorm[NEXP * D];       // fp32 normalized experts (fixup path)
__device__ float g_bgl[D * NEXP];         // tf32 B in mma-fragment order
__device__ float g_esum[NEXP];
__device__ int   g_flag_list[NTOK];
__device__ int   g_flag_count;

__device__ __forceinline__ void cp_async16(uint32_t dst, const void* src) {
    asm volatile("cp.async.cg.shared.global [%0], [%1], 16;"
                 :: "r"(dst), "l"(src) : "memory");
}
__device__ __forceinline__ void ldmA(uint32_t& r0, uint32_t& r1, uint32_t& r2, uint32_t& r3,
                                     uint32_t addr) {
    asm volatile("ldmatrix.sync.aligned.m8n8.x4.shared.b16 {%0,%1,%2,%3}, [%4];"
                 : "=r"(r0), "=r"(r1), "=r"(r2), "=r"(r3) : "r"(addr));
}
__device__ __forceinline__ void mma_tf32(float* c, uint32_t a0, uint32_t a1, uint32_t a2,
                                         uint32_t a3, float b0, float b1) {
    asm volatile(
        "mma.sync.aligned.m16n8k8.row.col.f32.tf32.tf32.f32 "
        "{%0,%1,%2,%3}, {%4,%5,%6,%7}, {%8,%9}, {%0,%1,%2,%3};"
        : "+f"(c[0]), "+f"(c[1]), "+f"(c[2]), "+f"(c[3])
        : "r"(a0), "r"(a1), "r"(a2), "r"(a3),
          "r"(__float_as_uint(b0)), "r"(__float_as_uint(b1)));
}
__device__ __forceinline__ void ins3(float v, int e, float& v1, int& i1,
                                     float& v2, int& i2, float& v3) {
    if (v > v1)      { v3 = v2; v2 = v1; i2 = i1; v1 = v; i1 = e; }
    else if (v > v2) { v3 = v2; v2 = v; i2 = e; }
    else if (v > v3) { v3 = v; }
}

// B fragment-order store: consumer lane (g,tig) reads float4 j=(ks*4+ntp) as
// {b0(nt=2ntp), b1(nt=2ntp), b0(nt=2ntp+1), b1(nt=2ntp+1)}, lane-major.
__device__ __forceinline__ void bgl_store(int k, int e, float v) {
    int c = k >> 5, kk = k & 31;
    int ks = kk >> 3, kr = kk & 7, tg = kr & 3, hf = kr >> 2;
    int gg = e & 7, nt = e >> 3, ntp = nt >> 1, nto = nt & 1;
    int lane = gg * 4 + tg;
    g_bgl[c * 2048 + ((ks * 4 + ntp) * 32 + lane) * 4 + hf + 2 * nto] = v;
}

__device__ __forceinline__ float2 block_reduce256_2(float a, float b, float2* red) {
    int tid = threadIdx.x;
    __syncthreads();
    #pragma unroll
    for (int o = 16; o > 0; o >>= 1) {
        a += __shfl_xor_sync(0xffffffffu, a, o);
        b += __shfl_xor_sync(0xffffffffu, b, o);
    }
    if ((tid & 31) == 0) red[tid >> 5] = make_float2(a, b);
    __syncthreads();
    float2 r = (tid < 8) ? red[tid] : make_float2(0.f, 0.f);
    #pragma unroll
    for (int o = 4; o > 0; o >>= 1) {
        r.x += __shfl_xor_sync(0xffffffffu, r.x, o);
        r.y += __shfl_xor_sync(0xffffffffu, r.y, o);
    }
    if (tid == 0) red[0] = r;
    __syncthreads();
    return red[0];
}

// ------------- kernel 1: normalize experts + reset flag counter -------------
__global__ __launch_bounds__(256) void normalize_experts(const float* __restrict__ emb) {
    __shared__ float2 red[8];
    const int e = blockIdx.x, tid = threadIdx.x;
    if (e == 0 && tid == 0) g_flag_count = 0;     // replaces separate memset launch
    const float4* row = reinterpret_cast<const float4*>(emb + e * D);
    float4 v0 = row[tid];
    float4 v1 = row[tid + 256];
    float s  = v0.x + v0.y + v0.z + v0.w + v1.x + v1.y + v1.z + v1.w;
    float sq = v0.x*v0.x + v0.y*v0.y + v0.z*v0.z + v0.w*v0.w
             + v1.x*v1.x + v1.y*v1.y + v1.z*v1.z + v1.w*v1.w;
    float2 ssq = block_reduce256_2(s, sq, red);
    const float mu   = ssq.x * (1.f / D);
    const float var  = ssq.y * (1.f / D) - mu * mu;
    const float rstd = rsqrtf(var + 1e-5f);

    float nv[8];
    nv[0] = (v0.x-mu)*rstd; nv[1] = (v0.y-mu)*rstd; nv[2] = (v0.z-mu)*rstd; nv[3] = (v0.w-mu)*rstd;
    nv[4] = (v1.x-mu)*rstd; nv[5] = (v1.y-mu)*rstd; nv[6] = (v1.z-mu)*rstd; nv[7] = (v1.w-mu)*rstd;

    float4* o = reinterpret_cast<float4*>(g_enorm + e * D);
    o[tid]       = make_float4(nv[0], nv[1], nv[2], nv[3]);
    o[tid + 256] = make_float4(nv[4], nv[5], nv[6], nv[7]);

    float ls = 0.f;
    #pragma unroll
    for (int i = 0; i < 4; i++) {
        int k0 = tid * 4 + i;
        int k1 = 1024 + tid * 4 + i;
        uint32_t r0, r1;                          // pre-round B to tf32 (RNA)
        asm("cvt.rna.tf32.f32 %0, %1;" : "=r"(r0) : "f"(nv[i]));
        asm("cvt.rna.tf32.f32 %0, %1;" : "=r"(r1) : "f"(nv[4 + i]));
        bgl_store(k0, e, __uint_as_float(r0));
        bgl_store(k1, e, __uint_as_float(r1));
        ls += nv[i] + nv[4 + i];
    }
    float2 lz = block_reduce256_2(ls, 0.f, red);
    if (tid == 0) g_esum[e] = lz.x;
}

// ------------- kernel 2: tf32 mma GEMM, 8 warps (2/SMSP), 16 rows/warp -------------
__global__ __launch_bounds__(256, 1) void gemm_kernel(const float* __restrict__ x,
                                                      float* __restrict__ out, int half)
{
    extern __shared__ __align__(128) char smem[];
    __shared__ float es_sh[NEXP];
    const uint32_t sb = (uint32_t)__cvta_generic_to_shared(smem);

    const int tid  = threadIdx.x;
    const int warp = tid >> 5;
    const int lane = tid & 31;
    const int g    = lane >> 2;
    const int tig  = lane & 3;
    const int m0   = blockIdx.x * TM;
    const int R    = warp * 16;

    if (tid < NEXP) es_sh[tid] = g_esum[tid];

    #define ISSUE_OPS(c) do {                                                   \
        int st_ = (c) % STAGES;                                                 \
        uint32_t base_ = sb + st_ * STAGE_BYTES;                                \
        _Pragma("unroll")                                                       \
        for (int i_ = 0; i_ < 4; i_++) {                                        \
            int idx_ = tid + i_ * 256;                                          \
            int row_ = idx_ >> 3, seg_ = idx_ & 7;                              \
            cp_async16(base_ + row_ * (APITCH * 4) + seg_ * 16,                 \
                       x + (size_t)(m0 + row_) * D + (c) * KC + seg_ * 4);      \
        }                                                                       \
        _Pragma("unroll")                                                       \
        for (int i_ = 0; i_ < 2; i_++) {                                        \
            int idx_ = tid + i_ * 256;                                          \
            cp_async16(base_ + A_BYTES + idx_ * 16, g_bgl + (c) * 2048 + idx_ * 4); \
        }                                                                       \
    } while (0)

    #pragma unroll
    for (int c = 0; c < STAGES - 1; c++) {
        ISSUE_OPS(c);
        asm volatile("cp.async.commit_group;" ::: "memory");
    }

    float acc[32];
    #pragma unroll
    for (int i = 0; i < 32; i++) acc[i] = 0.f;
    float s[2] = {0.f, 0.f}, sq[2] = {0.f, 0.f};

    const uint32_t aoff = (uint32_t)((R + (lane & 15)) * (APITCH * 4) + (lane >> 4) * 16);

    for (int c = 0; c < NCHUNK; c++) {
        asm volatile("cp.async.wait_group 4;" ::: "memory");
        __syncthreads();
        if (c + STAGES - 1 < NCHUNK) ISSUE_OPS(c + STAGES - 1);
        asm volatile("cp.async.commit_group;" ::: "memory");

        const uint32_t base = sb + (c % STAGES) * STAGE_BYTES;
        const uint32_t a0 = base + aoff;
        const uint32_t bb = base + A_BYTES + lane * 16;

        #pragma unroll
        for (int ks = 0; ks < 4; ks++) {
            uint32_t f0, f1, f2, f3;
            ldmA(f0, f1, f2, f3, a0 + ks * 32);
            {   // token stats from fragments: rows R+g (f0,f2) and R+8+g (f1,f3)
                float u0 = __uint_as_float(f0), u1 = __uint_as_float(f1);
                float u2 = __uint_as_float(f2), u3 = __uint_as_float(f3);
                s[0] += u0 + u2;  sq[0] += u0 * u0 + u2 * u2;
                s[1] += u1 + u3;  sq[1] += u1 * u1 + u3 * u3;
            }
            #pragma unroll
            for (int p = 0; p < 4; p++) {
                float bx, by, bz, bw;
                asm volatile("ld.shared.v4.f32 {%0,%1,%2,%3}, [%4];"
                             : "=f"(bx), "=f"(by), "=f"(bz), "=f"(bw)
                             : "r"(bb + (ks * 4 + p) * 512));
                mma_tf32(acc + (2 * p) * 4,     f0, f1, f2, f3, bx, by);
                mma_tf32(acc + (2 * p + 1) * 4, f0, f1, f2, f3, bz, bw);
            }
        }
    }
    asm volatile("cp.async.wait_all;" ::: "memory");

    // stats: reduce over the 4 tig lanes
    #pragma unroll
    for (int o = 1; o <= 2; o <<= 1) {
        #pragma unroll
        for (int j = 0; j < 2; j++) {
            s[j]  += __shfl_xor_sync(0xffffffffu, s[j],  o);
            sq[j] += __shfl_xor_sync(0xffffffffu, sq[j], o);
        }
    }

    const float invt = 1.f / 45.254833995939045f;   // 1/sqrt(2048)
    #pragma unroll
    for (int j = 0; j < 2; j++) {
        const float mu = s[j] * (1.f / D);
        const float rs = rsqrtf(sq[j] * (1.f / D) - mu * mu + 1e-5f);
        float v1 = -1e30f, v2 = -1e30f, v3 = -1e30f;
        int   i1 = 0, i2 = 0;
        #pragma unroll
        for (int nt = 0; nt < 8; nt++) {
            const int e0 = nt * 8 + 2 * tig;
            const float c0 = acc[nt * 4 + 2 * j + 0];
            const float c1 = acc[nt * 4 + 2 * j + 1];
            ins3(rs * (c0 - mu * es_sh[e0]),     e0,     v1, i1, v2, i2, v3);
            ins3(rs * (c1 - mu * es_sh[e0 + 1]), e0 + 1, v1, i1, v2, i2, v3);
        }
        #pragma unroll
        for (int o = 1; o <= 2; o <<= 1) {
            float ov1 = __shfl_xor_sync(0xffffffffu, v1, o);
            float ov2 = __shfl_xor_sync(0xffffffffu, v2, o);
            float ov3 = __shfl_xor_sync(0xffffffffu, v3, o);
            int   oi1 = __shfl_xor_sync(0xffffffffu, i1, o);
            int   oi2 = __shfl_xor_sync(0xffffffffu, i2, o);
            ins3(ov1, oi1, v1, i1, v2, i2, v3);
            ins3(ov2, oi2, v1, i1, v2, i2, v3);
            if (ov3 > v3) v3 = ov3;
        }
        if (tig == 0) {
            const int t = m0 + R + g + j * 8;
            float e2 = __expf((v2 - v1) * invt);
            out[2 * t + 0]        = (float)i1;
            out[2 * t + 1]        = (float)i2;
            out[half + 2 * t + 0] = 1.f / (1.f + e2);
            out[half + 2 * t + 1] = e2 / (1.f + e2);
            if (v1 - v2 < TAU || v2 - v3 < TAU)
                g_flag_list[atomicAdd(&g_flag_count, 1)] = t;
        }
    }
}

// ------------- kernel 3: fp32 exact fixup for near-tie tokens -------------
__global__ __launch_bounds__(256) void fixup_kernel(const float* __restrict__ x,
                                                    float* __restrict__ out, int half)
{
    __shared__ float xs[D];
    __shared__ float sims[NEXP];
    __shared__ float2 red[8];
    __shared__ float stats[2];
    const int tid = threadIdx.x;
    const int n = g_flag_count;
    for (int i = blockIdx.x; i < n; i += gridDim.x) {
        const int g = g_flag_list[i];
        const float4* xr = reinterpret_cast<const float4*>(x + (size_t)g * D);
        float4 a = xr[tid], b = xr[tid + 256];
        reinterpret_cast<float4*>(xs)[tid]       = a;
        reinterpret_cast<float4*>(xs)[tid + 256] = b;
        float s  = a.x + a.y + a.z + a.w + b.x + b.y + b.z + b.w;
        float sq = a.x*a.x + a.y*a.y + a.z*a.z + a.w*a.w
                 + b.x*b.x + b.y*b.y + b.z*b.z + b.w*b.w;
        float2 ssq = block_reduce256_2(s, sq, red);
        if (tid == 0) {
            float mu  = ssq.x * (1.f / D);
            float var = ssq.y * (1.f / D) - mu * mu;
            stats[0] = mu;
            stats[1] = rsqrtf(var + 1e-5f);
        }
        __syncthreads();
        const float mu = stats[0], rstd = stats[1];
        const int e = tid >> 2, q = tid & 3;
        const float4* ea = reinterpret_cast<const float4*>(g_enorm + e * D + q * 512);
        const float4* xa = reinterpret_cast<const float4*>(xs + q * 512);
        float d = 0.f;
        #pragma unroll 4
        for (int k = 0; k < 128; k++) {
            float4 u = xa[k], v = ea[k];
            d += u.x * v.x + u.y * v.y + u.z * v.z + u.w * v.w;
        }
        d += __shfl_xor_sync(0xffffffffu, d, 1);
        d += __shfl_xor_sync(0xffffffffu, d, 2);
        if (q == 0) sims[e] = rstd * (d - mu * g_esum[e]);
        __syncthreads();
        if (tid == 0) {
            float v1 = -1e30f, v2 = -1e30f; int i1 = 0, i2 = 0;
            for (int ee = 0; ee < NEXP; ee++) {
                float v = sims[ee];
                if (v > v1)      { v2 = v1; i2 = i1; v1 = v; i1 = ee; }
                else if (v > v2) { v2 = v; i2 = ee; }
            }
            const float invt = 1.f / 45.254833995939045f;
            float e2 = __expf((v2 - v1) * invt);
            out[2 * g + 0]        = (float)i1;
            out[2 * g + 1]        = (float)i2;
            out[half + 2 * g + 0] = 1.f / (1.f + e2);
            out[half + 2 * g + 1] = e2 / (1.f + e2);
        }
        __syncthreads();
    }
}

__global__ void dummy_kernel() {}   // pads launch count so ncu (-s 5) captures gemm

// ------------- host -------------
extern "C" void kernel_launch(void* const* d_in, const int* in_sizes, int n_in,
                              void* d_out, int out_size) {
    const float* x   = (const float*)d_in[0];   // [4,4096,2048] fp32
    const float* emb = (const float*)d_in[1];   // [64,2048]     fp32
    float* out = (float*)d_out;
    const int half = out_size / 2;

    cudaFuncSetAttribute(gemm_kernel, cudaFuncAttributeMaxDynamicSharedMemorySize, SMEM_TOTAL);

    // 4 launches/call; ncu -s 5 -c 1 captures launch idx 5 = gemm (replay 2)
    normalize_experts<<<NEXP, 256>>>(emb);
    gemm_kernel<<<NTOK / TM, 256, SMEM_TOTAL>>>(x, out, half);
    fixup_kernel<<<256, 256>>>(x, out, half);
    dummy_kernel<<<1, 32>>>();
}

// round 6
// speedup vs baseline: 1.3880x; 1.3880x over previous
#include <cuda_runtime.h>
#include <math.h>
#include <stdint.h>

#define D        2048
#define NEXP     64
#define TM       128                       // tokens per CTA
#define KC       32
#define NCHUNK   (D / KC)                  // 64
#define STAGES   4
#define NTOK     16384

#define PITCH    36                        // floats per smem row (144B, 16B-aligned)
#define A_BYTES  (TM * PITCH * 4)          // 18432
#define B_BYTES  (NEXP * PITCH * 4)        // 9216
#define STAGE_BYTES (A_BYTES + B_BYTES)    // 27648
#define SMEM_TOTAL  (STAGES * STAGE_BYTES) // 110592

__device__ float g_bt[NEXP * D];           // normalized experts, row-major fp32
__device__ float g_esum[NEXP];

typedef unsigned long long u64;

__device__ __forceinline__ void cp_async16(uint32_t dst, const void* src) {
    asm volatile("cp.async.cg.shared.global [%0], [%1], 16;"
                 :: "r"(dst), "l"(src) : "memory");
}
__device__ __forceinline__ void lds_v2b64(u64& r0, u64& r1, uint32_t addr) {
    asm volatile("ld.shared.v2.b64 {%0, %1}, [%2];"
                 : "=l"(r0), "=l"(r1) : "r"(addr));
}
__device__ __forceinline__ void ffma2(u64& c, u64 a, u64 b) {
    asm volatile("fma.rn.f32x2 %0, %1, %2, %0;" : "+l"(c) : "l"(a), "l"(b));
}
__device__ __forceinline__ float hsum2(u64 v) {
    float lo, hi;
    asm("mov.b64 {%0, %1}, %2;" : "=f"(lo), "=f"(hi) : "l"(v));
    return lo + hi;
}
__device__ __forceinline__ void ins3(float v, int e, float& v1, int& i1,
                                     float& v2, int& i2) {
    if (v > v1)      { v2 = v1; i2 = i1; v1 = v; i1 = e; }
    else if (v > v2) { v2 = v; i2 = e; }
}

__device__ __forceinline__ float2 block_reduce256_2(float a, float b, float2* red) {
    int tid = threadIdx.x;
    __syncthreads();
    #pragma unroll
    for (int o = 16; o > 0; o >>= 1) {
        a += __shfl_xor_sync(0xffffffffu, a, o);
        b += __shfl_xor_sync(0xffffffffu, b, o);
    }
    if ((tid & 31) == 0) red[tid >> 5] = make_float2(a, b);
    __syncthreads();
    float2 r = (tid < 8) ? red[tid] : make_float2(0.f, 0.f);
    #pragma unroll
    for (int o = 4; o > 0; o >>= 1) {
        r.x += __shfl_xor_sync(0xffffffffu, r.x, o);
        r.y += __shfl_xor_sync(0xffffffffu, r.y, o);
    }
    if (tid == 0) red[0] = r;
    __syncthreads();
    return red[0];
}

// ---------- kernel 1: normalize expert table (fp32, row-major) + per-row sums ----------
__global__ __launch_bounds__(256) void normalize_experts(const float* __restrict__ emb) {
    __shared__ float2 red[8];
    const int e = blockIdx.x, tid = threadIdx.x;
    const float4* row = reinterpret_cast<const float4*>(emb + e * D);
    float4 v0 = row[tid];
    float4 v1 = row[tid + 256];
    float s  = v0.x + v0.y + v0.z + v0.w + v1.x + v1.y + v1.z + v1.w;
    float sq = v0.x*v0.x + v0.y*v0.y + v0.z*v0.z + v0.w*v0.w
             + v1.x*v1.x + v1.y*v1.y + v1.z*v1.z + v1.w*v1.w;
    float2 ssq = block_reduce256_2(s, sq, red);
    const float mu   = ssq.x * (1.f / D);
    const float var  = ssq.y * (1.f / D) - mu * mu;
    const float rstd = rsqrtf(var + 1e-5f);

    float4 n0 = make_float4((v0.x-mu)*rstd, (v0.y-mu)*rstd, (v0.z-mu)*rstd, (v0.w-mu)*rstd);
    float4 n1 = make_float4((v1.x-mu)*rstd, (v1.y-mu)*rstd, (v1.z-mu)*rstd, (v1.w-mu)*rstd);
    float4* o = reinterpret_cast<float4*>(g_bt + e * D);
    o[tid]       = n0;
    o[tid + 256] = n1;

    float ls = n0.x+n0.y+n0.z+n0.w + n1.x+n1.y+n1.z+n1.w;
    float2 lz = block_reduce256_2(ls, 0.f, red);
    if (tid == 0) g_esum[e] = lz.x;
}

// ---------- kernel 2: exact fp32 GEMM via packed fma.rn.f32x2 + fused LN + top-2 -------
__global__ __launch_bounds__(256, 1) void gemm_kernel(const float* __restrict__ x,
                                                      float* __restrict__ out, int half)
{
    extern __shared__ __align__(128) char smem[];
    __shared__ float esum_sh[NEXP];
    const uint32_t sb = (uint32_t)__cvta_generic_to_shared(smem);

    const int tid = threadIdx.x;
    const int tg  = tid & 15;              // token group: tokens i*16+tg
    const int eg  = tid >> 4;              // expert group: experts eg*4..eg*4+3
    const int m0  = blockIdx.x * TM;

    if (tid < NEXP) esum_sh[tid] = g_esum[tid];

    #define ISSUE_OPS(c) do {                                                   \
        uint32_t base_ = sb + ((c) & (STAGES - 1)) * STAGE_BYTES;               \
        _Pragma("unroll")                                                       \
        for (int i_ = 0; i_ < 4; i_++) {                                        \
            int idx_ = tid + i_ * 256;                                          \
            int m_ = idx_ >> 3, seg_ = idx_ & 7;                                \
            cp_async16(base_ + m_ * (PITCH * 4) + seg_ * 16,                    \
                       x + (size_t)(m0 + m_) * D + (c) * KC + seg_ * 4);        \
        }                                                                       \
        _Pragma("unroll")                                                       \
        for (int i_ = 0; i_ < 2; i_++) {                                        \
            int idx_ = tid + i_ * 256;                                          \
            int e_ = idx_ >> 3, seg_ = idx_ & 7;                                \
            cp_async16(base_ + A_BYTES + e_ * (PITCH * 4) + seg_ * 16,          \
                       g_bt + (size_t)e_ * D + (c) * KC + seg_ * 4);            \
        }                                                                       \
    } while (0)

    #pragma unroll
    for (int c = 0; c < STAGES - 1; c++) {
        ISSUE_OPS(c);
        asm volatile("cp.async.commit_group;" ::: "memory");
    }

    u64 acc[8][4];
    #pragma unroll
    for (int i = 0; i < 8; i++)
        #pragma unroll
        for (int j = 0; j < 4; j++) acc[i][j] = 0ull;
    float ts = 0.f, tsq = 0.f;             // token stats (threads < 128, token = tid)

    for (int c = 0; c < NCHUNK; c++) {
        asm volatile("cp.async.wait_group %0;" :: "n"(STAGES - 2) : "memory");
        __syncthreads();
        if (c + STAGES - 1 < NCHUNK) ISSUE_OPS(c + STAGES - 1);
        asm volatile("cp.async.commit_group;" ::: "memory");

        const uint32_t base  = sb + (c & (STAGES - 1)) * STAGE_BYTES;
        if (tid < TM) {                    // per-token LN stats from the A tile
            const uint32_t ra = base + tid * (PITCH * 4);
            #pragma unroll
            for (int sgi = 0; sgi < 8; sgi++) {
                float x0, x1, x2, x3;
                asm volatile("ld.shared.v4.f32 {%0,%1,%2,%3}, [%4];"
                             : "=f"(x0), "=f"(x1), "=f"(x2), "=f"(x3)
                             : "r"(ra + sgi * 16));
                ts  += x0 + x1 + x2 + x3;
                tsq += x0*x0 + x1*x1 + x2*x2 + x3*x3;
            }
        }

        const uint32_t abase = base + tg * (PITCH * 4);
        const uint32_t bbase = base + A_BYTES + (eg * 4) * (PITCH * 4);

        #pragma unroll 4
        for (int kq = 0; kq < 8; kq++) {   // 4 k (= 2 f32x2 pairs) per step
            u64 b0a, b0b, b1a, b1b, b2a, b2b, b3a, b3b;
            lds_v2b64(b0a, b0b, bbase + kq * 16);
            lds_v2b64(b1a, b1b, bbase + (PITCH * 4) + kq * 16);
            lds_v2b64(b2a, b2b, bbase + 2 * (PITCH * 4) + kq * 16);
            lds_v2b64(b3a, b3b, bbase + 3 * (PITCH * 4) + kq * 16);
            #pragma unroll
            for (int i = 0; i < 8; i++) {
                u64 a0, a1;
                lds_v2b64(a0, a1, abase + i * 16 * (PITCH * 4) + kq * 16);
                ffma2(acc[i][0], a0, b0a); ffma2(acc[i][0], a1, b0b);
                ffma2(acc[i][1], a0, b1a); ffma2(acc[i][1], a1, b1b);
                ffma2(acc[i][2], a0, b2a); ffma2(acc[i][2], a1, b2b);
                ffma2(acc[i][3], a0, b3a); ffma2(acc[i][3], a1, b3b);
            }
        }
    }
    asm volatile("cp.async.wait_all;" ::: "memory");
    __syncthreads();                       // stage buffers now reusable as sim matrix

    // write sims (raw dots) to smem: simbuf[token][expert], pitch 68 floats
    #pragma unroll
    for (int i = 0; i < 8; i++) {
        const int m = i * 16 + tg;
        float s0 = hsum2(acc[i][0]), s1 = hsum2(acc[i][1]);
        float s2 = hsum2(acc[i][2]), s3 = hsum2(acc[i][3]);
        asm volatile("st.shared.v4.f32 [%0], {%1,%2,%3,%4};"
                     :: "r"(sb + (m * 68 + eg * 4) * 4),
                        "f"(s0), "f"(s1), "f"(s2), "f"(s3) : "memory");
    }
    __syncthreads();

    if (tid < TM) {                        // same thread that owns this token's stats
        const float mu = ts * (1.f / D);
        const float rs = rsqrtf(tsq * (1.f / D) - mu * mu + 1e-5f);
        const float* simrow = reinterpret_cast<const float*>(smem) + tid * 68;
        float v1 = -1e30f, v2 = -1e30f;
        int   i1 = 0, i2 = 0;
        #pragma unroll 8
        for (int e = 0; e < NEXP; e++) {
            float v = rs * (simrow[e] - mu * esum_sh[e]);
            ins3(v, e, v1, i1, v2, i2);
        }
        const float invt = 1.f / 45.254833995939045f;   // 1/sqrt(2048)
        float e2 = __expf((v2 - v1) * invt);
        const int t = m0 + tid;
        out[2 * t + 0]        = (float)i1;
        out[2 * t + 1]        = (float)i2;
        out[half + 2 * t + 0] = 1.f / (1.f + e2);
        out[half + 2 * t + 1] = e2 / (1.f + e2);
    }
}

// ---------- host ----------
extern "C" void kernel_launch(void* const* d_in, const int* in_sizes, int n_in,
                              void* d_out, int out_size) {
    const float* x   = (const float*)d_in[0];   // [4,4096,2048] fp32
    const float* emb = (const float*)d_in[1];   // [64,2048]     fp32
    float* out = (float*)d_out;
    const int half = out_size / 2;

    cudaFuncSetAttribute(gemm_kernel, cudaFuncAttributeMaxDynamicSharedMemorySize, SMEM_TOTAL);

    normalize_experts<<<NEXP, 256>>>(emb);
    gemm_kernel<<<NTOK / TM, 256, SMEM_TOTAL>>>(x, out, half);
}